// round 14
// baseline (speedup 1.0000x reference)
#include <cuda_runtime.h>
#include <cuda_fp16.h>
#include <math.h>
#include <stdint.h>

#define BSZ 8
#define SEQ 2048
#define EMB 768
#define MROWS (BSZ*SEQ)
#define P_SCALE 1024.0f

// ---------------------------------------------------------------------------
// Scratch (device globals; allocation forbidden in kernel_launch)
// ---------------------------------------------------------------------------
__device__ __align__(256) __half g_xh[MROWS*EMB];
__device__ __align__(256) __half g_Wqh[EMB*EMB];
__device__ __align__(256) __half g_Wkh[EMB*EMB];
__device__ __align__(256) __half g_Wvh[EMB*EMB];
__device__ __align__(256) __half g_Woh[EMB*EMB];
__device__ __align__(256) __half g_Qh[MROWS*EMB];
__device__ __align__(256) __half g_Kh[MROWS*EMB];
__device__ __align__(256) __half g_Vh[MROWS*EMB];                  // V hi, row-major [b,s,e]
__device__ __align__(256) __half g_Ph[(size_t)BSZ*SEQ*SEQ];        // fp16 scores -> probs (in place)
__device__ __align__(256) __half g_Ch[MROWS*EMB];

// ---------------------------------------------------------------------------
// helpers
// ---------------------------------------------------------------------------
__device__ __forceinline__ uint32_t smem_u32(const void* p) {
    uint32_t a;
    asm("{ .reg .u64 t; cvta.to.shared.u64 t, %1; cvt.u32.u64 %0, t; }" : "=r"(a) : "l"(p));
    return a;
}
__device__ __forceinline__ void cpasync16(uint32_t s, const void* g) {
    asm volatile("cp.async.cg.shared.global [%0], [%1], 16;" :: "r"(s), "l"(g));
}
__device__ __forceinline__ void cp_commit() { asm volatile("cp.async.commit_group;"); }

__device__ __forceinline__ void ldm_x4(uint32_t (&r)[4], uint32_t a) {
    asm volatile("ldmatrix.sync.aligned.m8n8.x4.shared.b16 {%0,%1,%2,%3}, [%4];"
        : "=r"(r[0]), "=r"(r[1]), "=r"(r[2]), "=r"(r[3]) : "r"(a));
}
__device__ __forceinline__ void ldm_x4_t(uint32_t (&r)[4], uint32_t a) {
    asm volatile("ldmatrix.sync.aligned.m8n8.x4.trans.shared.b16 {%0,%1,%2,%3}, [%4];"
        : "=r"(r[0]), "=r"(r[1]), "=r"(r[2]), "=r"(r[3]) : "r"(a));
}
__device__ __forceinline__ void mma16816(float (&d)[4], const uint32_t (&a)[4],
                                         uint32_t b0, uint32_t b1) {
    asm volatile("mma.sync.aligned.m16n8k16.row.col.f32.f16.f16.f32 "
        "{%0,%1,%2,%3}, {%4,%5,%6,%7}, {%8,%9}, {%0,%1,%2,%3};"
        : "+f"(d[0]), "+f"(d[1]), "+f"(d[2]), "+f"(d[3])
        : "r"(a[0]), "r"(a[1]), "r"(a[2]), "r"(a[3]), "r"(b0), "r"(b1));
}
__device__ __forceinline__ uint32_t pack_h2(__half a, __half b) {
    __half2 t(a, b);
    return *reinterpret_cast<uint32_t*>(&t);
}

// K-chunk = 64 halfs: row = 128B data + 16B pad (conflict-free ldmatrix)
#define ROWB    144
#define TILEB_A (128*ROWB)              // 18432 (A tile: 128 rows)
#define TILEB_B (256*ROWB)              // 36864 (B tile: 256 rows)

// Per-segment output descriptor (passed by value; selected per CTA by blockIdx.x)
struct BSeg {
    const __half* Bh;
    const float*  bias;
    __half*       outHi;
    float         scale;
};

// ---------------------------------------------------------------------------
// fp16 warp-MMA GEMM: D[m,n] = sum_k A[m,k]*B[n,k] (both K-major), fp32 accum.
// CTA tile 128x256, Kc=64, 8 warps (2x4, warp tile 64x64), 1 CTA/SM,
// single-sync 3-stage cp.async.
// OUTMODE 0: fp32 out (+bias). OUTMODE 1: fp16 hi out ((acc+bias)*scale).
// Segmented B: CTAs pick {s0,s1,s2} by blockIdx.x / segW (merged QKV launch).
// ---------------------------------------------------------------------------
#define NSTAGE 3
#define STAGEB (TILEB_A + TILEB_B)      // 55296

template <int OUTMODE>
__global__ void __launch_bounds__(256, 1)
gemm_mma(const __half* __restrict__ Ah,
         int K, long ldA, long ldB, long sAb, long sBb,
         float* __restrict__ outF, long ldOut, long obs,
         BSeg s0, BSeg s1, BSeg s2, int segW)
{
    extern __shared__ char smem[];
    const uint32_t sb = smem_u32(smem);

    const int tid    = threadIdx.x;
    const int lane   = tid & 31;
    const int wid    = tid >> 5;
    const int warp_m = wid & 1;         // 2 warps over M (64 rows each)
    const int warp_n = wid >> 1;        // 4 warps over N (64 cols each)

    int bxi = blockIdx.x;
    BSeg seg = s0;
    if (segW > 0) {
        if (bxi >= 2 * segW)      { seg = s2; bxi -= 2 * segW; }
        else if (bxi >= segW)     { seg = s1; bxi -= segW; }
    }
    const int by = blockIdx.y * 128;
    const int bx = bxi * 256;
    const int bz = blockIdx.z;

    Ah += (long)bz * sAb;
    const __half* Bh = seg.Bh + (long)bz * sBb;

    // loader: A 1024 16B-chunks (4/thread), B 2048 (8/thread)
    auto load_chunk = [&](int kc, int stage) {
        const long kk = (long)kc * 64;
        const uint32_t s0a = sb + stage * STAGEB;
#pragma unroll
        for (int i = 0; i < 4; ++i) {
            const int c   = tid + i * 256;
            const int row = c >> 3;
            const int g   = c & 7;
            cpasync16(s0a + row * ROWB + g * 16,
                      Ah + (long)(by + row) * ldA + kk + g * 8);
        }
        const uint32_t s0b = s0a + TILEB_A;
#pragma unroll
        for (int i = 0; i < 8; ++i) {
            const int c   = tid + i * 256;
            const int row = c >> 3;
            const int g   = c & 7;
            cpasync16(s0b + row * ROWB + g * 16,
                      Bh + (long)(bx + row) * ldB + kk + g * 8);
        }
    };

    float acc[4][8][4];
#pragma unroll
    for (int i = 0; i < 4; ++i)
#pragma unroll
        for (int j = 0; j < 8; ++j)
#pragma unroll
            for (int e = 0; e < 4; ++e) acc[i][j][e] = 0.f;

    const int nChunks = K >> 6;

#pragma unroll
    for (int i = 0; i < NSTAGE - 1; ++i) {
        load_chunk(i, i);
        cp_commit();
    }

    const int rl = lane & 7;
    const int gq = lane >> 3;
    const uint32_t aoff = (uint32_t)((warp_m * 64 + (gq & 1) * 8 + rl) * ROWB + (gq >> 1) * 16);
    const uint32_t boff = (uint32_t)((warp_n * 64 + (gq >> 1) * 8 + rl) * ROWB + (gq & 1) * 16);

    // single-sync loop: wait(kc ready) -> sync -> load (kc-1) slot -> compute kc
    for (int kc = 0; kc < nChunks; ++kc) {
        asm volatile("cp.async.wait_group %0;" :: "n"(NSTAGE - 2));
        __syncthreads();
        const int pf = kc + NSTAGE - 1;
        if (pf < nChunks) load_chunk(pf, pf % NSTAGE);
        cp_commit();

        const uint32_t st = sb + (kc % NSTAGE) * STAGEB;
#pragma unroll
        for (int ks = 0; ks < 4; ++ks) {
            const uint32_t kb = ks * 32;
            uint32_t ah[4][4];
#pragma unroll
            for (int i = 0; i < 4; ++i)
                ldm_x4(ah[i], st + aoff + i * (16 * ROWB) + kb);
            uint32_t bh[4][4];
#pragma unroll
            for (int g = 0; g < 4; ++g)
                ldm_x4(bh[g], st + TILEB_A + boff + g * (16 * ROWB) + kb);
#pragma unroll
            for (int i = 0; i < 4; ++i)
#pragma unroll
                for (int j = 0; j < 8; ++j) {
                    const int g = j >> 1, o = (j & 1) * 2;
                    mma16816(acc[i][j], ah[i], bh[g][o], bh[g][o + 1]);
                }
        }
    }

    // ---------------- epilogue ----------------
    const int r_in = lane >> 2;
    const int c_in = (lane & 3) * 2;

#pragma unroll
    for (int i = 0; i < 4; ++i) {
#pragma unroll
        for (int j = 0; j < 8; ++j) {
            const int row0 = by + warp_m * 64 + i * 16 + r_in;
            const int row1 = row0 + 8;
            const int col  = bx + warp_n * 64 + j * 8 + c_in;
            const float b0 = seg.bias ? seg.bias[col]     : 0.f;
            const float b1 = seg.bias ? seg.bias[col + 1] : 0.f;

            if (OUTMODE == 0) {
                float2 v0 = make_float2(acc[i][j][0] + b0, acc[i][j][1] + b1);
                float2 v1 = make_float2(acc[i][j][2] + b0, acc[i][j][3] + b1);
                *reinterpret_cast<float2*>(outF + (long)bz * obs + (long)row0 * ldOut + col) = v0;
                *reinterpret_cast<float2*>(outF + (long)bz * obs + (long)row1 * ldOut + col) = v1;
            } else {
                float v00 = (acc[i][j][0] + b0) * seg.scale, v01 = (acc[i][j][1] + b1) * seg.scale;
                float v10 = (acc[i][j][2] + b0) * seg.scale, v11 = (acc[i][j][3] + b1) * seg.scale;
                const long o0 = (long)bz * obs + (long)row0 * ldOut + col;
                const long o1 = (long)bz * obs + (long)row1 * ldOut + col;
                *reinterpret_cast<uint32_t*>(seg.outHi + o0) =
                    pack_h2(__float2half_rn(v00), __float2half_rn(v01));
                *reinterpret_cast<uint32_t*>(seg.outHi + o1) =
                    pack_h2(__float2half_rn(v10), __float2half_rn(v11));
            }
        }
    }
}

// ---------------------------------------------------------------------------
// PV GEMM: C[m,e] = sum_s P[m,s] * V[s,e]. A = Ph K-major; B = V row-major
// [s,e] via trans-ldmatrix from swizzled [k=64 x 512B] smem tiles.
// CTA 128x256, warp tile 64x64, Kc=64, 3 stages, 1 CTA/SM. Hi out, *scale.
// ---------------------------------------------------------------------------
#define PV_BTILE 32768                       // 64 rows x 512B, swizzled
#define PV_STAGE (TILEB_A + PV_BTILE)        // 51200
#define PV_NST   3

__global__ void __launch_bounds__(256, 1)
gemm_pv(const __half* __restrict__ Ah, const __half* __restrict__ Bv,
        int K, long ldA, long ldB, long sAb, long sBb,
        __half* __restrict__ outHi, float scale, long ldOut, long obs)
{
    extern __shared__ char smem[];
    const uint32_t sb = smem_u32(smem);

    const int tid    = threadIdx.x;
    const int lane   = tid & 31;
    const int wid    = tid >> 5;
    const int warp_m = wid & 1;
    const int warp_n = wid >> 1;
    const int by     = blockIdx.y * 128;
    const int bx     = blockIdx.x * 256;
    const int bz     = blockIdx.z;

    Ah += (long)bz * sAb;
    Bv += (long)bz * sBb;

    auto load_chunk = [&](int kc, int stage) {
        const long kk = (long)kc * 64;
        const uint32_t s0 = sb + stage * PV_STAGE;
        // A tile: 128 rows x 128B (+pad), 1024 chunks, 4/thread
#pragma unroll
        for (int i = 0; i < 4; ++i) {
            const int c   = tid + i * 256;
            const int row = c >> 3;
            const int g   = c & 7;
            cpasync16(s0 + row * ROWB + g * 16,
                      Ah + (long)(by + row) * ldA + kk + g * 8);
        }
        // B tile: 64 rows x 512B swizzled, 2048 chunks, 8/thread
        const uint32_t b0 = s0 + TILEB_A;
#pragma unroll
        for (int i = 0; i < 8; ++i) {
            const int c  = tid + i * 256;
            const int bk = c >> 5;
            const int bg = c & 31;
            cpasync16(b0 + bk * 512 + ((bg ^ (bk & 7)) * 16),
                      Bv + (long)(kk + bk) * ldB + bx + bg * 8);
        }
    };

    float acc[4][8][4];
#pragma unroll
    for (int i = 0; i < 4; ++i)
#pragma unroll
        for (int j = 0; j < 8; ++j)
#pragma unroll
            for (int e = 0; e < 4; ++e) acc[i][j][e] = 0.f;

    const int nChunks = K >> 6;

#pragma unroll
    for (int i = 0; i < PV_NST - 1; ++i) {
        load_chunk(i, i);
        cp_commit();
    }

    const int rl = lane & 7;
    const int gq = lane >> 3;
    const uint32_t aoff = (uint32_t)((warp_m * 64 + (gq & 1) * 8 + rl) * ROWB + (gq >> 1) * 16);
    const int brow_in = (gq & 1) * 8 + rl;            // k within 16-block
    const int bcol16  = warp_n * 8 + (gq >> 1);       // + g*2 at use site (16B units)

    for (int kc = 0; kc < nChunks; ++kc) {
        asm volatile("cp.async.wait_group %0;" :: "n"(PV_NST - 2));
        __syncthreads();
        const int pf = kc + PV_NST - 1;
        if (pf < nChunks) load_chunk(pf, pf % PV_NST);
        cp_commit();

        const uint32_t st = sb + (kc % PV_NST) * PV_STAGE;
        const uint32_t bt0 = st + TILEB_A;
#pragma unroll
        for (int ks = 0; ks < 4; ++ks) {
            uint32_t ah[4][4];
#pragma unroll
            for (int i = 0; i < 4; ++i)
                ldm_x4(ah[i], st + aoff + i * (16 * ROWB) + ks * 32);
            uint32_t bt[4][4];
            const int row = ks * 16 + brow_in;
#pragma unroll
            for (int g = 0; g < 4; ++g) {
                const int c = (bcol16 + g * 2) ^ (row & 7);
                ldm_x4_t(bt[g], bt0 + row * 512 + c * 16);
            }
#pragma unroll
            for (int i = 0; i < 4; ++i)
#pragma unroll
                for (int j = 0; j < 8; ++j) {
                    const int g = j >> 1, o = (j & 1) * 2;
                    mma16816(acc[i][j], ah[i], bt[g][o], bt[g][o + 1]);
                }
        }
    }

    // epilogue: hi only, *scale
    const int r_in = lane >> 2;
    const int c_in = (lane & 3) * 2;
#pragma unroll
    for (int i = 0; i < 4; ++i) {
#pragma unroll
        for (int j = 0; j < 8; ++j) {
            const int row0 = by + warp_m * 64 + i * 16 + r_in;
            const int row1 = row0 + 8;
            const int col  = bx + warp_n * 64 + j * 8 + c_in;
            float v00 = acc[i][j][0] * scale, v01 = acc[i][j][1] * scale;
            float v10 = acc[i][j][2] * scale, v11 = acc[i][j][3] * scale;
            const long o0 = (long)bz * obs + (long)row0 * ldOut + col;
            const long o1 = (long)bz * obs + (long)row1 * ldOut + col;
            *reinterpret_cast<uint32_t*>(outHi + o0) =
                pack_h2(__float2half_rn(v00), __float2half_rn(v01));
            *reinterpret_cast<uint32_t*>(outHi + o1) =
                pack_h2(__float2half_rn(v10), __float2half_rn(v11));
        }
    }
}

// ---------------------------------------------------------------------------
// Elementwise convert: fp32 -> fp16 (hi only), 8 elems/thread
// ---------------------------------------------------------------------------
__global__ void cvt_h(const float4* __restrict__ in, __half* __restrict__ oh, int n8)
{
    const int i = blockIdx.x * blockDim.x + threadIdx.x;
    if (i >= n8) return;
    const float4 a = in[2 * i];
    const float4 b = in[2 * i + 1];
    uint4 o;
    o.x = pack_h2(__float2half_rn(a.x), __float2half_rn(a.y));
    o.y = pack_h2(__float2half_rn(a.z), __float2half_rn(a.w));
    o.z = pack_h2(__float2half_rn(b.x), __float2half_rn(b.y));
    o.w = pack_h2(__float2half_rn(b.z), __float2half_rn(b.w));
    *reinterpret_cast<uint4*>(oh + 8 * (long)i) = o;
}

// ---------------------------------------------------------------------------
// Weight transpose (hi only), 4 weights in one launch (blockIdx.z selects):
// W[K,N] fp32 -> Wt hi [N,K] fp16
// ---------------------------------------------------------------------------
struct WPair { const float* W; __half* oh; };

__global__ void wsplit4(WPair w0, WPair w1, WPair w2, WPair w3)
{
    __shared__ float t[32][33];
    const WPair wp = (blockIdx.z == 0) ? w0 : (blockIdx.z == 1) ? w1
                   : (blockIdx.z == 2) ? w2 : w3;
    const int n0 = blockIdx.x * 32, k0 = blockIdx.y * 32;
    const int tx = threadIdx.x, ty = threadIdx.y;
#pragma unroll
    for (int i = 0; i < 32; i += 8)
        t[ty + i][tx] = wp.W[(long)(k0 + ty + i) * EMB + n0 + tx];
    __syncthreads();
#pragma unroll
    for (int i = 0; i < 32; i += 8) {
        const long o = (long)(n0 + ty + i) * EMB + k0 + tx;
        wp.oh[o] = __float2half_rn(t[tx][ty + i]);
    }
}

// ---------------------------------------------------------------------------
// Row softmax over fp16 raw scores, in place, emitting fp16 probs x P_SCALE.
// ---------------------------------------------------------------------------
__global__ void __launch_bounds__(256)
softmax_h(__half* __restrict__ Ph)
{
    __shared__ float sred[8];
    __shared__ float sbc[2];
    const int tid = threadIdx.x;
    const long base = (long)blockIdx.x * SEQ;

    float v[8];
    {
        const uint4 a = *reinterpret_cast<const uint4*>(Ph + base + tid * 8);
        const __half2* h = reinterpret_cast<const __half2*>(&a);
#pragma unroll
        for (int j = 0; j < 4; ++j) {
            float2 f = __half22float2(h[j]);
            v[2 * j]     = f.x;
            v[2 * j + 1] = f.y;
        }
    }

    float m = v[0];
#pragma unroll
    for (int j = 1; j < 8; j++) m = fmaxf(m, v[j]);
#pragma unroll
    for (int o = 16; o > 0; o >>= 1) m = fmaxf(m, __shfl_xor_sync(0xffffffffu, m, o));
    if ((tid & 31) == 0) sred[tid >> 5] = m;
    __syncthreads();
    if (tid == 0) {
        float t = sred[0];
#pragma unroll
        for (int w = 1; w < 8; w++) t = fmaxf(t, sred[w]);
        sbc[0] = t;
    }
    __syncthreads();
    m = sbc[0];

    float s = 0.f;
#pragma unroll
    for (int j = 0; j < 8; j++) { v[j] = __expf(v[j] - m); s += v[j]; }
#pragma unroll
    for (int o = 16; o > 0; o >>= 1) s += __shfl_xor_sync(0xffffffffu, s, o);
    __syncthreads();
    if ((tid & 31) == 0) sred[tid >> 5] = s;
    __syncthreads();
    if (tid == 0) {
        float t = sred[0];
#pragma unroll
        for (int w = 1; w < 8; w++) t += sred[w];
        sbc[1] = t;
    }
    __syncthreads();
    const float inv = P_SCALE / sbc[1];

    uint4 o;
    o.x = pack_h2(__float2half_rn(v[0] * inv), __float2half_rn(v[1] * inv));
    o.y = pack_h2(__float2half_rn(v[2] * inv), __float2half_rn(v[3] * inv));
    o.z = pack_h2(__float2half_rn(v[4] * inv), __float2half_rn(v[5] * inv));
    o.w = pack_h2(__float2half_rn(v[6] * inv), __float2half_rn(v[7] * inv));
    *reinterpret_cast<uint4*>(Ph + base + tid * 8) = o;
}

// ---------------------------------------------------------------------------
// Host side
// ---------------------------------------------------------------------------
extern "C" void kernel_launch(void* const* d_in, const int* in_sizes, int n_in,
                              void* d_out, int out_size)
{
    const float* x  = (const float*)d_in[0];
    const float* Wq = (const float*)d_in[1];
    const float* bq = (const float*)d_in[2];
    const float* Wk = (const float*)d_in[3];
    const float* bk = (const float*)d_in[4];
    const float* Wv = (const float*)d_in[5];
    const float* bv = (const float*)d_in[6];
    const float* Wo = (const float*)d_in[7];
    const float* bo = (const float*)d_in[8];
    float* out = (float*)d_out;

    void *xh, *Wqh, *Wkh, *Wvh, *Woh;
    void *Qh, *Kh, *Vh, *Ph, *Ch;
    cudaGetSymbolAddress(&xh, g_xh);
    cudaGetSymbolAddress(&Wqh, g_Wqh);
    cudaGetSymbolAddress(&Wkh, g_Wkh);
    cudaGetSymbolAddress(&Wvh, g_Wvh);
    cudaGetSymbolAddress(&Woh, g_Woh);
    cudaGetSymbolAddress(&Qh, g_Qh);
    cudaGetSymbolAddress(&Kh, g_Kh);
    cudaGetSymbolAddress(&Vh, g_Vh);
    cudaGetSymbolAddress(&Ph, g_Ph);
    cudaGetSymbolAddress(&Ch, g_Ch);

    const int SM2 = NSTAGE * STAGEB;     // 165888 (gemm_mma: 3 stages)
    const int SMP = PV_NST * PV_STAGE;   // 153600 (PV: 3 stages)
    cudaFuncSetAttribute(gemm_mma<0>, cudaFuncAttributeMaxDynamicSharedMemorySize, SM2);
    cudaFuncSetAttribute(gemm_mma<1>, cudaFuncAttributeMaxDynamicSharedMemorySize, SM2);
    cudaFuncSetAttribute(gemm_pv,     cudaFuncAttributeMaxDynamicSharedMemorySize, SMP);

    const float scl = 1.0f / sqrtf((float)EMB);
    const dim3 blk(256);
    const BSeg nil = {nullptr, nullptr, nullptr, 1.0f};

    // 1) convert inputs to fp16 hi (x + all 4 weights, 2 launches)
    {
        const int n8 = MROWS * EMB / 8;
        cvt_h<<<(n8 + 255) / 256, 256>>>((const float4*)x, (__half*)xh, n8);
        WPair w0 = {Wq, (__half*)Wqh};
        WPair w1 = {Wk, (__half*)Wkh};
        WPair w2 = {Wv, (__half*)Wvh};
        WPair w3 = {Wo, (__half*)Woh};
        wsplit4<<<dim3(24, 24, 4), dim3(32, 8)>>>(w0, w1, w2, w3);
    }

    // 2) merged QKV projections: one launch, segmented B/out, hi out
    //    N tile = 256 -> 3 x-tiles per matrix, segW = 3
    {
        BSeg sq = {(const __half*)Wqh, bq, (__half*)Qh, scl};
        BSeg sk = {(const __half*)Wkh, bk, (__half*)Kh, 1.0f};
        BSeg sv = {(const __half*)Wvh, bv, (__half*)Vh, 1.0f};
        gemm_mma<1><<<dim3(9, 128, 1), blk, SM2>>>(
            (const __half*)xh,
            EMB, EMB, EMB, 0, 0,
            nullptr, EMB, 0, sq, sk, sv, 3);
    }

    // 3) scores = Q' @ K^T (scale folded into Q), fp16 raw scores out
    {
        BSeg sc = {(const __half*)Kh, nullptr, (__half*)Ph, 1.0f};
        gemm_mma<1><<<dim3(8, 16, 8), blk, SM2>>>(
            (const __half*)Qh,
            EMB, EMB, EMB, (long)SEQ * EMB, (long)SEQ * EMB,
            nullptr, SEQ, (long)SEQ * SEQ, sc, nil, nil, 0);
    }

    // 4) softmax in place: fp16 scores -> fp16 probs (x P_SCALE)
    softmax_h<<<MROWS, 256>>>((__half*)Ph);

    // 5) ctx = P @ V, B = V row-major via trans-ldmatrix, K=2048
    gemm_pv<<<dim3(3, 16, 8), blk, SMP>>>(
        (const __half*)Ph, (const __half*)Vh,
        SEQ, SEQ, EMB, (long)SEQ * SEQ, (long)SEQ * EMB,
        (__half*)Ch, 1.0f / P_SCALE, EMB, (long)SEQ * EMB);

    // 6) out = C @ Wo^T + bo, fp32
    {
        BSeg so = {(const __half*)Woh, bo, nullptr, 1.0f};
        gemm_mma<0><<<dim3(3, 128, 1), blk, SM2>>>(
            (const __half*)Ch,
            EMB, EMB, EMB, 0, 0,
            out, EMB, 0, so, nil, nil, 0);
    }
}

// round 15
// speedup vs baseline: 1.0003x; 1.0003x over previous
#include <cuda_runtime.h>
#include <cuda_fp16.h>
#include <math.h>
#include <stdint.h>

#define BSZ 8
#define SEQ 2048
#define EMB 768
#define MROWS (BSZ*SEQ)
#define P_SCALE 1024.0f

// ---------------------------------------------------------------------------
// Scratch (device globals; allocation forbidden in kernel_launch)
// ---------------------------------------------------------------------------
__device__ __align__(256) __half g_xh[MROWS*EMB];
__device__ __align__(256) __half g_Wqh[EMB*EMB];
__device__ __align__(256) __half g_Wkh[EMB*EMB];
__device__ __align__(256) __half g_Wvh[EMB*EMB];
__device__ __align__(256) __half g_Woh[EMB*EMB];
__device__ __align__(256) __half g_Qh[MROWS*EMB];
__device__ __align__(256) __half g_Kh[MROWS*EMB];
__device__ __align__(256) __half g_Vh[MROWS*EMB];                  // V hi, row-major [b,s,e]
__device__ __align__(256) __half g_Ph[(size_t)BSZ*SEQ*SEQ];        // fp16 scores -> probs (in place)
__device__ __align__(256) __half g_Ch[MROWS*EMB];

// ---------------------------------------------------------------------------
// helpers
// ---------------------------------------------------------------------------
__device__ __forceinline__ uint32_t smem_u32(const void* p) {
    uint32_t a;
    asm("{ .reg .u64 t; cvta.to.shared.u64 t, %1; cvt.u32.u64 %0, t; }" : "=r"(a) : "l"(p));
    return a;
}
__device__ __forceinline__ void cpasync16(uint32_t s, const void* g) {
    asm volatile("cp.async.cg.shared.global [%0], [%1], 16;" :: "r"(s), "l"(g));
}
__device__ __forceinline__ void cp_commit() { asm volatile("cp.async.commit_group;"); }

__device__ __forceinline__ void ldm_x4(uint32_t (&r)[4], uint32_t a) {
    asm volatile("ldmatrix.sync.aligned.m8n8.x4.shared.b16 {%0,%1,%2,%3}, [%4];"
        : "=r"(r[0]), "=r"(r[1]), "=r"(r[2]), "=r"(r[3]) : "r"(a));
}
__device__ __forceinline__ void ldm_x4_t(uint32_t (&r)[4], uint32_t a) {
    asm volatile("ldmatrix.sync.aligned.m8n8.x4.trans.shared.b16 {%0,%1,%2,%3}, [%4];"
        : "=r"(r[0]), "=r"(r[1]), "=r"(r[2]), "=r"(r[3]) : "r"(a));
}
__device__ __forceinline__ void mma16816(float (&d)[4], const uint32_t (&a)[4],
                                         uint32_t b0, uint32_t b1) {
    asm volatile("mma.sync.aligned.m16n8k16.row.col.f32.f16.f16.f32 "
        "{%0,%1,%2,%3}, {%4,%5,%6,%7}, {%8,%9}, {%0,%1,%2,%3};"
        : "+f"(d[0]), "+f"(d[1]), "+f"(d[2]), "+f"(d[3])
        : "r"(a[0]), "r"(a[1]), "r"(a[2]), "r"(a[3]), "r"(b0), "r"(b1));
}
__device__ __forceinline__ uint32_t pack_h2(__half a, __half b) {
    __half2 t(a, b);
    return *reinterpret_cast<uint32_t*>(&t);
}

// K-chunk = 64 halfs: row = 128B data + 16B pad (conflict-free ldmatrix)
#define ROWB    144
#define TILEB_A (128*ROWB)              // 18432 (A tile: 128 rows)
#define TILEB_B (256*ROWB)              // 36864 (B tile: 256 rows)
#define NTHREADS 512

// Per-segment output descriptor (passed by value; selected per CTA by blockIdx.x)
struct BSeg {
    const __half* Bh;
    const float*  bias;
    __half*       outHi;
    float         scale;
};

// ---------------------------------------------------------------------------
// fp16 warp-MMA GEMM: D[m,n] = sum_k A[m,k]*B[n,k] (both K-major), fp32 accum.
// CTA tile 128x256, 512 threads, 16 warps (4x4, warp tile 32x64), 1 CTA/SM,
// Kc=64, single-sync 3-stage cp.async.
// OUTMODE 0: fp32 out (+bias). OUTMODE 1: fp16 hi out ((acc+bias)*scale).
// Segmented B: CTAs pick {s0,s1,s2} by blockIdx.x / segW (merged QKV launch).
// ---------------------------------------------------------------------------
#define NSTAGE 3
#define STAGEB (TILEB_A + TILEB_B)      // 55296

template <int OUTMODE>
__global__ void __launch_bounds__(NTHREADS, 1)
gemm_mma(const __half* __restrict__ Ah,
         int K, long ldA, long ldB, long sAb, long sBb,
         float* __restrict__ outF, long ldOut, long obs,
         BSeg s0, BSeg s1, BSeg s2, int segW)
{
    extern __shared__ char smem[];
    const uint32_t sb = smem_u32(smem);

    const int tid    = threadIdx.x;
    const int lane   = tid & 31;
    const int wid    = tid >> 5;
    const int warp_m = wid & 3;         // 4 warps over M (32 rows each)
    const int warp_n = wid >> 2;        // 4 warps over N (64 cols each)

    int bxi = blockIdx.x;
    BSeg seg = s0;
    if (segW > 0) {
        if (bxi >= 2 * segW)      { seg = s2; bxi -= 2 * segW; }
        else if (bxi >= segW)     { seg = s1; bxi -= segW; }
    }
    const int by = blockIdx.y * 128;
    const int bx = bxi * 256;
    const int bz = blockIdx.z;

    Ah += (long)bz * sAb;
    const __half* Bh = seg.Bh + (long)bz * sBb;

    // loader: A 1024 16B-chunks (2/thread), B 2048 (4/thread)
    auto load_chunk = [&](int kc, int stage) {
        const long kk = (long)kc * 64;
        const uint32_t s0a = sb + stage * STAGEB;
#pragma unroll
        for (int i = 0; i < 2; ++i) {
            const int c   = tid + i * NTHREADS;
            const int row = c >> 3;
            const int g   = c & 7;
            cpasync16(s0a + row * ROWB + g * 16,
                      Ah + (long)(by + row) * ldA + kk + g * 8);
        }
        const uint32_t s0b = s0a + TILEB_A;
#pragma unroll
        for (int i = 0; i < 4; ++i) {
            const int c   = tid + i * NTHREADS;
            const int row = c >> 3;
            const int g   = c & 7;
            cpasync16(s0b + row * ROWB + g * 16,
                      Bh + (long)(bx + row) * ldB + kk + g * 8);
        }
    };

    float acc[2][8][4];
#pragma unroll
    for (int i = 0; i < 2; ++i)
#pragma unroll
        for (int j = 0; j < 8; ++j)
#pragma unroll
            for (int e = 0; e < 4; ++e) acc[i][j][e] = 0.f;

    const int nChunks = K >> 6;

#pragma unroll
    for (int i = 0; i < NSTAGE - 1; ++i) {
        load_chunk(i, i);
        cp_commit();
    }

    const int rl = lane & 7;
    const int gq = lane >> 3;
    const uint32_t aoff = (uint32_t)((warp_m * 32 + (gq & 1) * 8 + rl) * ROWB + (gq >> 1) * 16);
    const uint32_t boff = (uint32_t)((warp_n * 64 + (gq >> 1) * 8 + rl) * ROWB + (gq & 1) * 16);

    // single-sync loop: wait(kc ready) -> sync -> load (kc-1) slot -> compute kc
    for (int kc = 0; kc < nChunks; ++kc) {
        asm volatile("cp.async.wait_group %0;" :: "n"(NSTAGE - 2));
        __syncthreads();
        const int pf = kc + NSTAGE - 1;
        if (pf < nChunks) load_chunk(pf, pf % NSTAGE);
        cp_commit();

        const uint32_t st = sb + (kc % NSTAGE) * STAGEB;
#pragma unroll
        for (int ks = 0; ks < 4; ++ks) {
            const uint32_t kb = ks * 32;
            uint32_t ah[2][4];
#pragma unroll
            for (int i = 0; i < 2; ++i)
                ldm_x4(ah[i], st + aoff + i * (16 * ROWB) + kb);
            uint32_t bh[4][4];
#pragma unroll
            for (int g = 0; g < 4; ++g)
                ldm_x4(bh[g], st + TILEB_A + boff + g * (16 * ROWB) + kb);
#pragma unroll
            for (int i = 0; i < 2; ++i)
#pragma unroll
                for (int j = 0; j < 8; ++j) {
                    const int g = j >> 1, o = (j & 1) * 2;
                    mma16816(acc[i][j], ah[i], bh[g][o], bh[g][o + 1]);
                }
        }
    }

    // ---------------- epilogue ----------------
    const int r_in = lane >> 2;
    const int c_in = (lane & 3) * 2;

#pragma unroll
    for (int i = 0; i < 2; ++i) {
#pragma unroll
        for (int j = 0; j < 8; ++j) {
            const int row0 = by + warp_m * 32 + i * 16 + r_in;
            const int row1 = row0 + 8;
            const int col  = bx + warp_n * 64 + j * 8 + c_in;
            const float b0 = seg.bias ? seg.bias[col]     : 0.f;
            const float b1 = seg.bias ? seg.bias[col + 1] : 0.f;

            if (OUTMODE == 0) {
                float2 v0 = make_float2(acc[i][j][0] + b0, acc[i][j][1] + b1);
                float2 v1 = make_float2(acc[i][j][2] + b0, acc[i][j][3] + b1);
                *reinterpret_cast<float2*>(outF + (long)bz * obs + (long)row0 * ldOut + col) = v0;
                *reinterpret_cast<float2*>(outF + (long)bz * obs + (long)row1 * ldOut + col) = v1;
            } else {
                float v00 = (acc[i][j][0] + b0) * seg.scale, v01 = (acc[i][j][1] + b1) * seg.scale;
                float v10 = (acc[i][j][2] + b0) * seg.scale, v11 = (acc[i][j][3] + b1) * seg.scale;
                const long o0 = (long)bz * obs + (long)row0 * ldOut + col;
                const long o1 = (long)bz * obs + (long)row1 * ldOut + col;
                *reinterpret_cast<uint32_t*>(seg.outHi + o0) =
                    pack_h2(__float2half_rn(v00), __float2half_rn(v01));
                *reinterpret_cast<uint32_t*>(seg.outHi + o1) =
                    pack_h2(__float2half_rn(v10), __float2half_rn(v11));
            }
        }
    }
}

// ---------------------------------------------------------------------------
// PV GEMM: C[m,e] = sum_s P[m,s] * V[s,e]. A = Ph K-major; B = V row-major
// [s,e] via trans-ldmatrix from swizzled [k=64 x 512B] smem tiles.
// CTA 128x256, 512 threads, warp tile 32x64, Kc=64, 3 stages, 1 CTA/SM.
// ---------------------------------------------------------------------------
#define PV_BTILE 32768                       // 64 rows x 512B, swizzled
#define PV_STAGE (TILEB_A + PV_BTILE)        // 51200
#define PV_NST   3

__global__ void __launch_bounds__(NTHREADS, 1)
gemm_pv(const __half* __restrict__ Ah, const __half* __restrict__ Bv,
        int K, long ldA, long ldB, long sAb, long sBb,
        __half* __restrict__ outHi, float scale, long ldOut, long obs)
{
    extern __shared__ char smem[];
    const uint32_t sb = smem_u32(smem);

    const int tid    = threadIdx.x;
    const int lane   = tid & 31;
    const int wid    = tid >> 5;
    const int warp_m = wid & 3;
    const int warp_n = wid >> 2;
    const int by     = blockIdx.y * 128;
    const int bx     = blockIdx.x * 256;
    const int bz     = blockIdx.z;

    Ah += (long)bz * sAb;
    Bv += (long)bz * sBb;

    auto load_chunk = [&](int kc, int stage) {
        const long kk = (long)kc * 64;
        const uint32_t s0 = sb + stage * PV_STAGE;
        // A tile: 128 rows x 128B (+pad), 1024 chunks, 2/thread
#pragma unroll
        for (int i = 0; i < 2; ++i) {
            const int c   = tid + i * NTHREADS;
            const int row = c >> 3;
            const int g   = c & 7;
            cpasync16(s0 + row * ROWB + g * 16,
                      Ah + (long)(by + row) * ldA + kk + g * 8);
        }
        // B tile: 64 rows x 512B swizzled, 2048 chunks, 4/thread
        const uint32_t b0 = s0 + TILEB_A;
#pragma unroll
        for (int i = 0; i < 4; ++i) {
            const int c  = tid + i * NTHREADS;
            const int bk = c >> 5;
            const int bg = c & 31;
            cpasync16(b0 + bk * 512 + ((bg ^ (bk & 7)) * 16),
                      Bv + (long)(kk + bk) * ldB + bx + bg * 8);
        }
    };

    float acc[2][8][4];
#pragma unroll
    for (int i = 0; i < 2; ++i)
#pragma unroll
        for (int j = 0; j < 8; ++j)
#pragma unroll
            for (int e = 0; e < 4; ++e) acc[i][j][e] = 0.f;

    const int nChunks = K >> 6;

#pragma unroll
    for (int i = 0; i < PV_NST - 1; ++i) {
        load_chunk(i, i);
        cp_commit();
    }

    const int rl = lane & 7;
    const int gq = lane >> 3;
    const uint32_t aoff = (uint32_t)((warp_m * 32 + (gq & 1) * 8 + rl) * ROWB + (gq >> 1) * 16);
    const int brow_in = (gq & 1) * 8 + rl;            // k within 16-block
    const int bcol16  = warp_n * 8 + (gq >> 1);       // + g*2 at use site (16B units, 32 per row)

    for (int kc = 0; kc < nChunks; ++kc) {
        asm volatile("cp.async.wait_group %0;" :: "n"(PV_NST - 2));
        __syncthreads();
        const int pf = kc + PV_NST - 1;
        if (pf < nChunks) load_chunk(pf, pf % PV_NST);
        cp_commit();

        const uint32_t st = sb + (kc % PV_NST) * PV_STAGE;
        const uint32_t bt0 = st + TILEB_A;
#pragma unroll
        for (int ks = 0; ks < 4; ++ks) {
            uint32_t ah[2][4];
#pragma unroll
            for (int i = 0; i < 2; ++i)
                ldm_x4(ah[i], st + aoff + i * (16 * ROWB) + ks * 32);
            uint32_t bt[4][4];
            const int row = ks * 16 + brow_in;
#pragma unroll
            for (int g = 0; g < 4; ++g) {
                const int c = (bcol16 + g * 2) ^ (row & 7);
                ldm_x4_t(bt[g], bt0 + row * 512 + c * 16);
            }
#pragma unroll
            for (int i = 0; i < 2; ++i)
#pragma unroll
                for (int j = 0; j < 8; ++j) {
                    const int g = j >> 1, o = (j & 1) * 2;
                    mma16816(acc[i][j], ah[i], bt[g][o], bt[g][o + 1]);
                }
        }
    }

    // epilogue: hi only, *scale
    const int r_in = lane >> 2;
    const int c_in = (lane & 3) * 2;
#pragma unroll
    for (int i = 0; i < 2; ++i) {
#pragma unroll
        for (int j = 0; j < 8; ++j) {
            const int row0 = by + warp_m * 32 + i * 16 + r_in;
            const int row1 = row0 + 8;
            const int col  = bx + warp_n * 64 + j * 8 + c_in;
            float v00 = acc[i][j][0] * scale, v01 = acc[i][j][1] * scale;
            float v10 = acc[i][j][2] * scale, v11 = acc[i][j][3] * scale;
            const long o0 = (long)bz * obs + (long)row0 * ldOut + col;
            const long o1 = (long)bz * obs + (long)row1 * ldOut + col;
            *reinterpret_cast<uint32_t*>(outHi + o0) =
                pack_h2(__float2half_rn(v00), __float2half_rn(v01));
            *reinterpret_cast<uint32_t*>(outHi + o1) =
                pack_h2(__float2half_rn(v10), __float2half_rn(v11));
        }
    }
}

// ---------------------------------------------------------------------------
// Elementwise convert: fp32 -> fp16 (hi only), 8 elems/thread
// ---------------------------------------------------------------------------
__global__ void cvt_h(const float4* __restrict__ in, __half* __restrict__ oh, int n8)
{
    const int i = blockIdx.x * blockDim.x + threadIdx.x;
    if (i >= n8) return;
    const float4 a = in[2 * i];
    const float4 b = in[2 * i + 1];
    uint4 o;
    o.x = pack_h2(__float2half_rn(a.x), __float2half_rn(a.y));
    o.y = pack_h2(__float2half_rn(a.z), __float2half_rn(a.w));
    o.z = pack_h2(__float2half_rn(b.x), __float2half_rn(b.y));
    o.w = pack_h2(__float2half_rn(b.z), __float2half_rn(b.w));
    *reinterpret_cast<uint4*>(oh + 8 * (long)i) = o;
}

// ---------------------------------------------------------------------------
// Weight transpose (hi only), 4 weights in one launch (blockIdx.z selects):
// W[K,N] fp32 -> Wt hi [N,K] fp16
// ---------------------------------------------------------------------------
struct WPair { const float* W; __half* oh; };

__global__ void wsplit4(WPair w0, WPair w1, WPair w2, WPair w3)
{
    __shared__ float t[32][33];
    const WPair wp = (blockIdx.z == 0) ? w0 : (blockIdx.z == 1) ? w1
                   : (blockIdx.z == 2) ? w2 : w3;
    const int n0 = blockIdx.x * 32, k0 = blockIdx.y * 32;
    const int tx = threadIdx.x, ty = threadIdx.y;
#pragma unroll
    for (int i = 0; i < 32; i += 8)
        t[ty + i][tx] = wp.W[(long)(k0 + ty + i) * EMB + n0 + tx];
    __syncthreads();
#pragma unroll
    for (int i = 0; i < 32; i += 8) {
        const long o = (long)(n0 + ty + i) * EMB + k0 + tx;
        wp.oh[o] = __float2half_rn(t[tx][ty + i]);
    }
}

// ---------------------------------------------------------------------------
// Row softmax over fp16 raw scores, in place, emitting fp16 probs x P_SCALE.
// ---------------------------------------------------------------------------
__global__ void __launch_bounds__(256)
softmax_h(__half* __restrict__ Ph)
{
    __shared__ float sred[8];
    __shared__ float sbc[2];
    const int tid = threadIdx.x;
    const long base = (long)blockIdx.x * SEQ;

    float v[8];
    {
        const uint4 a = *reinterpret_cast<const uint4*>(Ph + base + tid * 8);
        const __half2* h = reinterpret_cast<const __half2*>(&a);
#pragma unroll
        for (int j = 0; j < 4; ++j) {
            float2 f = __half22float2(h[j]);
            v[2 * j]     = f.x;
            v[2 * j + 1] = f.y;
        }
    }

    float m = v[0];
#pragma unroll
    for (int j = 1; j < 8; j++) m = fmaxf(m, v[j]);
#pragma unroll
    for (int o = 16; o > 0; o >>= 1) m = fmaxf(m, __shfl_xor_sync(0xffffffffu, m, o));
    if ((tid & 31) == 0) sred[tid >> 5] = m;
    __syncthreads();
    if (tid == 0) {
        float t = sred[0];
#pragma unroll
        for (int w = 1; w < 8; w++) t = fmaxf(t, sred[w]);
        sbc[0] = t;
    }
    __syncthreads();
    m = sbc[0];

    float s = 0.f;
#pragma unroll
    for (int j = 0; j < 8; j++) { v[j] = __expf(v[j] - m); s += v[j]; }
#pragma unroll
    for (int o = 16; o > 0; o >>= 1) s += __shfl_xor_sync(0xffffffffu, s, o);
    __syncthreads();
    if ((tid & 31) == 0) sred[tid >> 5] = s;
    __syncthreads();
    if (tid == 0) {
        float t = sred[0];
#pragma unroll
        for (int w = 1; w < 8; w++) t += sred[w];
        sbc[1] = t;
    }
    __syncthreads();
    const float inv = P_SCALE / sbc[1];

    uint4 o;
    o.x = pack_h2(__float2half_rn(v[0] * inv), __float2half_rn(v[1] * inv));
    o.y = pack_h2(__float2half_rn(v[2] * inv), __float2half_rn(v[3] * inv));
    o.z = pack_h2(__float2half_rn(v[4] * inv), __float2half_rn(v[5] * inv));
    o.w = pack_h2(__float2half_rn(v[6] * inv), __float2half_rn(v[7] * inv));
    *reinterpret_cast<uint4*>(Ph + base + tid * 8) = o;
}

// ---------------------------------------------------------------------------
// Host side
// ---------------------------------------------------------------------------
extern "C" void kernel_launch(void* const* d_in, const int* in_sizes, int n_in,
                              void* d_out, int out_size)
{
    const float* x  = (const float*)d_in[0];
    const float* Wq = (const float*)d_in[1];
    const float* bq = (const float*)d_in[2];
    const float* Wk = (const float*)d_in[3];
    const float* bk = (const float*)d_in[4];
    const float* Wv = (const float*)d_in[5];
    const float* bv = (const float*)d_in[6];
    const float* Wo = (const float*)d_in[7];
    const float* bo = (const float*)d_in[8];
    float* out = (float*)d_out;

    void *xh, *Wqh, *Wkh, *Wvh, *Woh;
    void *Qh, *Kh, *Vh, *Ph, *Ch;
    cudaGetSymbolAddress(&xh, g_xh);
    cudaGetSymbolAddress(&Wqh, g_Wqh);
    cudaGetSymbolAddress(&Wkh, g_Wkh);
    cudaGetSymbolAddress(&Wvh, g_Wvh);
    cudaGetSymbolAddress(&Woh, g_Woh);
    cudaGetSymbolAddress(&Qh, g_Qh);
    cudaGetSymbolAddress(&Kh, g_Kh);
    cudaGetSymbolAddress(&Vh, g_Vh);
    cudaGetSymbolAddress(&Ph, g_Ph);
    cudaGetSymbolAddress(&Ch, g_Ch);

    const int SM2 = NSTAGE * STAGEB;     // 165888 (gemm_mma: 3 stages)
    const int SMP = PV_NST * PV_STAGE;   // 153600 (PV: 3 stages)
    cudaFuncSetAttribute(gemm_mma<0>, cudaFuncAttributeMaxDynamicSharedMemorySize, SM2);
    cudaFuncSetAttribute(gemm_mma<1>, cudaFuncAttributeMaxDynamicSharedMemorySize, SM2);
    cudaFuncSetAttribute(gemm_pv,     cudaFuncAttributeMaxDynamicSharedMemorySize, SMP);

    const float scl = 1.0f / sqrtf((float)EMB);
    const dim3 blk(NTHREADS);
    const BSeg nil = {nullptr, nullptr, nullptr, 1.0f};

    // 1) convert inputs to fp16 hi (x + all 4 weights, 2 launches)
    {
        const int n8 = MROWS * EMB / 8;
        cvt_h<<<(n8 + 255) / 256, 256>>>((const float4*)x, (__half*)xh, n8);
        WPair w0 = {Wq, (__half*)Wqh};
        WPair w1 = {Wk, (__half*)Wkh};
        WPair w2 = {Wv, (__half*)Wvh};
        WPair w3 = {Wo, (__half*)Woh};
        wsplit4<<<dim3(24, 24, 4), dim3(32, 8)>>>(w0, w1, w2, w3);
    }

    // 2) merged QKV projections: one launch, segmented B/out, hi out
    //    N tile = 256 -> 3 x-tiles per matrix, segW = 3
    {
        BSeg sq = {(const __half*)Wqh, bq, (__half*)Qh, scl};
        BSeg sk = {(const __half*)Wkh, bk, (__half*)Kh, 1.0f};
        BSeg sv = {(const __half*)Wvh, bv, (__half*)Vh, 1.0f};
        gemm_mma<1><<<dim3(9, 128, 1), blk, SM2>>>(
            (const __half*)xh,
            EMB, EMB, EMB, 0, 0,
            nullptr, EMB, 0, sq, sk, sv, 3);
    }

    // 3) scores = Q' @ K^T (scale folded into Q), fp16 raw scores out
    {
        BSeg sc = {(const __half*)Kh, nullptr, (__half*)Ph, 1.0f};
        gemm_mma<1><<<dim3(8, 16, 8), blk, SM2>>>(
            (const __half*)Qh,
            EMB, EMB, EMB, (long)SEQ * EMB, (long)SEQ * EMB,
            nullptr, SEQ, (long)SEQ * SEQ, sc, nil, nil, 0);
    }

    // 4) softmax in place: fp16 scores -> fp16 probs (x P_SCALE)
    softmax_h<<<MROWS, 256>>>((__half*)Ph);

    // 5) ctx = P @ V, B = V row-major via trans-ldmatrix, K=2048
    gemm_pv<<<dim3(3, 16, 8), blk, SMP>>>(
        (const __half*)Ph, (const __half*)Vh,
        SEQ, SEQ, EMB, (long)SEQ * SEQ, (long)SEQ * EMB,
        (__half*)Ch, 1.0f / P_SCALE, EMB, (long)SEQ * EMB);

    // 6) out = C @ Wo^T + bo, fp32
    {
        BSeg so = {(const __half*)Woh, bo, nullptr, 1.0f};
        gemm_mma<0><<<dim3(3, 128, 1), blk, SM2>>>(
            (const __half*)Ch,
            EMB, EMB, EMB, 0, 0,
            out, EMB, 0, so, nil, nil, 0);
    }
}

// round 16
// speedup vs baseline: 1.0632x; 1.0629x over previous
#include <cuda_runtime.h>
#include <cuda_fp16.h>
#include <math.h>
#include <stdint.h>

#define BSZ 8
#define SEQ 2048
#define EMB 768
#define MROWS (BSZ*SEQ)
#define P_SCALE 1024.0f

// ---------------------------------------------------------------------------
// Scratch (device globals; allocation forbidden in kernel_launch)
// ---------------------------------------------------------------------------
__device__ __align__(256) __half g_xh[MROWS*EMB];
__device__ __align__(256) __half g_Wqh[EMB*EMB];
__device__ __align__(256) __half g_Wkh[EMB*EMB];
__device__ __align__(256) __half g_Wvh[EMB*EMB];
__device__ __align__(256) __half g_Woh[EMB*EMB];
__device__ __align__(256) __half g_Qh[MROWS*EMB];
__device__ __align__(256) __half g_Kh[MROWS*EMB];
__device__ __align__(256) __half g_Vh[MROWS*EMB];                  // V hi, row-major [b,s,e]
__device__ __align__(256) __half g_Ph[(size_t)BSZ*SEQ*SEQ];        // fp16 scores -> probs (in place)
__device__ __align__(256) __half g_Ch[MROWS*EMB];

// ---------------------------------------------------------------------------
// helpers
// ---------------------------------------------------------------------------
__device__ __forceinline__ uint32_t smem_u32(const void* p) {
    uint32_t a;
    asm("{ .reg .u64 t; cvta.to.shared.u64 t, %1; cvt.u32.u64 %0, t; }" : "=r"(a) : "l"(p));
    return a;
}
__device__ __forceinline__ void cpasync16(uint32_t s, const void* g) {
    asm volatile("cp.async.cg.shared.global [%0], [%1], 16;" :: "r"(s), "l"(g));
}
__device__ __forceinline__ void cp_commit() { asm volatile("cp.async.commit_group;"); }

__device__ __forceinline__ void ldm_x4(uint32_t (&r)[4], uint32_t a) {
    asm volatile("ldmatrix.sync.aligned.m8n8.x4.shared.b16 {%0,%1,%2,%3}, [%4];"
        : "=r"(r[0]), "=r"(r[1]), "=r"(r[2]), "=r"(r[3]) : "r"(a));
}
__device__ __forceinline__ void ldm_x4_t(uint32_t (&r)[4], uint32_t a) {
    asm volatile("ldmatrix.sync.aligned.m8n8.x4.trans.shared.b16 {%0,%1,%2,%3}, [%4];"
        : "=r"(r[0]), "=r"(r[1]), "=r"(r[2]), "=r"(r[3]) : "r"(a));
}
__device__ __forceinline__ void mma16816(float (&d)[4], const uint32_t (&a)[4],
                                         uint32_t b0, uint32_t b1) {
    asm volatile("mma.sync.aligned.m16n8k16.row.col.f32.f16.f16.f32 "
        "{%0,%1,%2,%3}, {%4,%5,%6,%7}, {%8,%9}, {%0,%1,%2,%3};"
        : "+f"(d[0]), "+f"(d[1]), "+f"(d[2]), "+f"(d[3])
        : "r"(a[0]), "r"(a[1]), "r"(a[2]), "r"(a[3]), "r"(b0), "r"(b1));
}
__device__ __forceinline__ uint32_t pack_h2(__half a, __half b) {
    __half2 t(a, b);
    return *reinterpret_cast<uint32_t*>(&t);
}

// K-chunk = 64 halfs: row = 128B data + 16B pad (conflict-free ldmatrix)
#define ROWB   144
#define TILEB  (128*ROWB)               // 18432 B

// Per-segment output descriptor (passed by value; selected per CTA by blockIdx.x)
struct BSeg {
    const __half* Bh;
    const float*  bias;
    __half*       outHi;
    float         scale;
};

// ---------------------------------------------------------------------------
// fp16 warp-MMA GEMM: D[m,n] = sum_k A[m,k]*B[n,k] (both K-major), fp32 accum.
// CTA 128x128, Kc=64, 8 warps (32x64), single-sync 3-stage cp.async, 2 CTA/SM.
// OUTMODE 0: fp32 out (+bias). OUTMODE 1: fp16 hi out ((acc+bias)*scale).
// Segmented B: CTAs pick {s0,s1,s2} by blockIdx.x / segW (merged QKV launch).
// ---------------------------------------------------------------------------
#define NSTAGE 3
#define STAGEB (2*TILEB)                // 36864

template <int OUTMODE>
__global__ void __launch_bounds__(256, 2)
gemm_mma(const __half* __restrict__ Ah,
         int K, long ldA, long ldB, long sAb, long sBb,
         float* __restrict__ outF, long ldOut, long obs,
         BSeg s0, BSeg s1, BSeg s2, int segW)
{
    extern __shared__ char smem[];
    const uint32_t sb = smem_u32(smem);

    const int tid    = threadIdx.x;
    const int lane   = tid & 31;
    const int wid    = tid >> 5;
    const int warp_m = wid & 3;
    const int warp_n = wid >> 2;

    int bxi = blockIdx.x;
    BSeg seg = s0;
    if (segW > 0) {
        if (bxi >= 2 * segW)      { seg = s2; bxi -= 2 * segW; }
        else if (bxi >= segW)     { seg = s1; bxi -= segW; }
    }
    const int by = blockIdx.y * 128;
    const int bx = bxi * 128;
    const int bz = blockIdx.z;

    Ah += (long)bz * sAb;
    const __half* Bh = seg.Bh + (long)bz * sBb;

    // loader: 1024 16B-chunks per tile, 4 per thread per tile
    auto load_chunk = [&](int kc, int stage) {
        const long kk = (long)kc * 64;
        const uint32_t s0a = sb + stage * STAGEB;
#pragma unroll
        for (int i = 0; i < 4; ++i) {
            const int c   = tid + i * 256;
            const int row = c >> 3;
            const int g   = c & 7;
            cpasync16(s0a + row * ROWB + g * 16,
                      Ah + (long)(by + row) * ldA + kk + g * 8);
            cpasync16(s0a + TILEB + row * ROWB + g * 16,
                      Bh + (long)(bx + row) * ldB + kk + g * 8);
        }
    };

    float acc[2][8][4];
#pragma unroll
    for (int i = 0; i < 2; ++i)
#pragma unroll
        for (int j = 0; j < 8; ++j)
#pragma unroll
            for (int e = 0; e < 4; ++e) acc[i][j][e] = 0.f;

    const int nChunks = K >> 6;

#pragma unroll
    for (int i = 0; i < NSTAGE - 1; ++i) {
        load_chunk(i, i);
        cp_commit();
    }

    const int rl = lane & 7;
    const int gq = lane >> 3;
    const uint32_t aoff = (uint32_t)((warp_m * 32 + (gq & 1) * 8 + rl) * ROWB + (gq >> 1) * 16);
    const uint32_t boff = (uint32_t)((warp_n * 64 + (gq >> 1) * 8 + rl) * ROWB + (gq & 1) * 16);

    // single-sync loop: wait(kc ready) -> sync -> load (kc-1) slot -> compute kc
    for (int kc = 0; kc < nChunks; ++kc) {
        asm volatile("cp.async.wait_group %0;" :: "n"(NSTAGE - 2));
        __syncthreads();
        const int pf = kc + NSTAGE - 1;
        if (pf < nChunks) load_chunk(pf, pf % NSTAGE);
        cp_commit();

        const uint32_t st = sb + (kc % NSTAGE) * STAGEB;
#pragma unroll
        for (int ks = 0; ks < 4; ++ks) {
            const uint32_t kb = ks * 32;
            uint32_t ah[2][4];
#pragma unroll
            for (int i = 0; i < 2; ++i)
                ldm_x4(ah[i], st + aoff + i * (16 * ROWB) + kb);
            uint32_t bh[4][4];
#pragma unroll
            for (int g = 0; g < 4; ++g)
                ldm_x4(bh[g], st + TILEB + boff + g * (16 * ROWB) + kb);
#pragma unroll
            for (int i = 0; i < 2; ++i)
#pragma unroll
                for (int j = 0; j < 8; ++j) {
                    const int g = j >> 1, o = (j & 1) * 2;
                    mma16816(acc[i][j], ah[i], bh[g][o], bh[g][o + 1]);
                }
        }
    }

    // ---------------- epilogue ----------------
    const int r_in = lane >> 2;
    const int c_in = (lane & 3) * 2;

#pragma unroll
    for (int i = 0; i < 2; ++i) {
#pragma unroll
        for (int j = 0; j < 8; ++j) {
            const int row0 = by + warp_m * 32 + i * 16 + r_in;
            const int row1 = row0 + 8;
            const int col  = bx + warp_n * 64 + j * 8 + c_in;
            const float b0 = seg.bias ? seg.bias[col]     : 0.f;
            const float b1 = seg.bias ? seg.bias[col + 1] : 0.f;

            if (OUTMODE == 0) {
                float2 v0 = make_float2(acc[i][j][0] + b0, acc[i][j][1] + b1);
                float2 v1 = make_float2(acc[i][j][2] + b0, acc[i][j][3] + b1);
                *reinterpret_cast<float2*>(outF + (long)bz * obs + (long)row0 * ldOut + col) = v0;
                *reinterpret_cast<float2*>(outF + (long)bz * obs + (long)row1 * ldOut + col) = v1;
            } else {
                float v00 = (acc[i][j][0] + b0) * seg.scale, v01 = (acc[i][j][1] + b1) * seg.scale;
                float v10 = (acc[i][j][2] + b0) * seg.scale, v11 = (acc[i][j][3] + b1) * seg.scale;
                const long o0 = (long)bz * obs + (long)row0 * ldOut + col;
                const long o1 = (long)bz * obs + (long)row1 * ldOut + col;
                *reinterpret_cast<uint32_t*>(seg.outHi + o0) =
                    pack_h2(__float2half_rn(v00), __float2half_rn(v01));
                *reinterpret_cast<uint32_t*>(seg.outHi + o1) =
                    pack_h2(__float2half_rn(v10), __float2half_rn(v11));
            }
        }
    }
}

// ---------------------------------------------------------------------------
// PV GEMM: C[m,e] = sum_s P[m,s] * V[s,e]. A = Ph K-major; B = V row-major
// [s,e] loaded via trans-ldmatrix from swizzled [k=64 x 256B] smem tiles.
// Single-sync 3-stage pipeline, Kc=64, 2 CTA/SM. Hi-only out, *scale.
// ---------------------------------------------------------------------------
#define PV_BTILE 16384                       // 64 rows x 256B, swizzled
#define PV_STAGE (TILEB + PV_BTILE)          // 34816
#define PV_NST   3

__global__ void __launch_bounds__(256, 2)
gemm_pv(const __half* __restrict__ Ah, const __half* __restrict__ Bv,
        int K, long ldA, long ldB, long sAb, long sBb,
        __half* __restrict__ outHi, float scale, long ldOut, long obs)
{
    extern __shared__ char smem[];
    const uint32_t sb = smem_u32(smem);

    const int tid    = threadIdx.x;
    const int lane   = tid & 31;
    const int wid    = tid >> 5;
    const int warp_m = wid & 3;
    const int warp_n = wid >> 2;
    const int by     = blockIdx.y * 128;
    const int bx     = blockIdx.x * 128;
    const int bz     = blockIdx.z;

    Ah += (long)bz * sAb;
    Bv += (long)bz * sBb;

    auto load_chunk = [&](int kc, int stage) {
        const long kk = (long)kc * 64;
        const uint32_t s0 = sb + stage * PV_STAGE;
        // A tile: 128 rows x 128B (+pad), 1024 chunks, 4/thread
#pragma unroll
        for (int i = 0; i < 4; ++i) {
            const int c   = tid + i * 256;
            const int row = c >> 3;
            const int g   = c & 7;
            cpasync16(s0 + row * ROWB + g * 16,
                      Ah + (long)(by + row) * ldA + kk + g * 8);
        }
        // B tile: 64 rows x 256B swizzled, 1024 chunks, 4/thread
        const uint32_t b0 = s0 + TILEB;
#pragma unroll
        for (int i = 0; i < 4; ++i) {
            const int c  = tid + i * 256;
            const int bk = c >> 4;
            const int bg = c & 15;
            cpasync16(b0 + bk * 256 + ((bg ^ (bk & 7)) * 16),
                      Bv + (long)(kk + bk) * ldB + bx + bg * 8);
        }
    };

    float acc[2][8][4];
#pragma unroll
    for (int i = 0; i < 2; ++i)
#pragma unroll
        for (int j = 0; j < 8; ++j)
#pragma unroll
            for (int e = 0; e < 4; ++e) acc[i][j][e] = 0.f;

    const int nChunks = K >> 6;

#pragma unroll
    for (int i = 0; i < PV_NST - 1; ++i) {
        load_chunk(i, i);
        cp_commit();
    }

    const int rl = lane & 7;
    const int gq = lane >> 3;
    const uint32_t aoff = (uint32_t)((warp_m * 32 + (gq & 1) * 8 + rl) * ROWB + (gq >> 1) * 16);
    const int brow_in = (gq & 1) * 8 + rl;            // k within 16-block
    const int bcol16  = warp_n * 8 + (gq >> 1);       // + g*2 at use site

    for (int kc = 0; kc < nChunks; ++kc) {
        asm volatile("cp.async.wait_group %0;" :: "n"(PV_NST - 2));
        __syncthreads();
        const int pf = kc + PV_NST - 1;
        if (pf < nChunks) load_chunk(pf, pf % PV_NST);
        cp_commit();

        const uint32_t st = sb + (kc % PV_NST) * PV_STAGE;
        const uint32_t bt0 = st + TILEB;
#pragma unroll
        for (int ks = 0; ks < 4; ++ks) {
            uint32_t ah[2][4];
#pragma unroll
            for (int i = 0; i < 2; ++i)
                ldm_x4(ah[i], st + aoff + i * (16 * ROWB) + ks * 32);
            uint32_t bt[4][4];
            const int row = ks * 16 + brow_in;
#pragma unroll
            for (int g = 0; g < 4; ++g) {
                const int c = (bcol16 + g * 2) ^ (row & 7);
                ldm_x4_t(bt[g], bt0 + row * 256 + c * 16);
            }
#pragma unroll
            for (int i = 0; i < 2; ++i)
#pragma unroll
                for (int j = 0; j < 8; ++j) {
                    const int g = j >> 1, o = (j & 1) * 2;
                    mma16816(acc[i][j], ah[i], bt[g][o], bt[g][o + 1]);
                }
        }
    }

    // epilogue: hi only, *scale
    const int r_in = lane >> 2;
    const int c_in = (lane & 3) * 2;
#pragma unroll
    for (int i = 0; i < 2; ++i) {
#pragma unroll
        for (int j = 0; j < 8; ++j) {
            const int row0 = by + warp_m * 32 + i * 16 + r_in;
            const int row1 = row0 + 8;
            const int col  = bx + warp_n * 64 + j * 8 + c_in;
            float v00 = acc[i][j][0] * scale, v01 = acc[i][j][1] * scale;
            float v10 = acc[i][j][2] * scale, v11 = acc[i][j][3] * scale;
            const long o0 = (long)bz * obs + (long)row0 * ldOut + col;
            const long o1 = (long)bz * obs + (long)row1 * ldOut + col;
            *reinterpret_cast<uint32_t*>(outHi + o0) =
                pack_h2(__float2half_rn(v00), __float2half_rn(v01));
            *reinterpret_cast<uint32_t*>(outHi + o1) =
                pack_h2(__float2half_rn(v10), __float2half_rn(v11));
        }
    }
}

// ---------------------------------------------------------------------------
// Elementwise convert: fp32 -> fp16 (hi only), 8 elems/thread
// ---------------------------------------------------------------------------
__global__ void cvt_h(const float4* __restrict__ in, __half* __restrict__ oh, int n8)
{
    const int i = blockIdx.x * blockDim.x + threadIdx.x;
    if (i >= n8) return;
    const float4 a = in[2 * i];
    const float4 b = in[2 * i + 1];
    uint4 o;
    o.x = pack_h2(__float2half_rn(a.x), __float2half_rn(a.y));
    o.y = pack_h2(__float2half_rn(a.z), __float2half_rn(a.w));
    o.z = pack_h2(__float2half_rn(b.x), __float2half_rn(b.y));
    o.w = pack_h2(__float2half_rn(b.z), __float2half_rn(b.w));
    *reinterpret_cast<uint4*>(oh + 8 * (long)i) = o;
}

// ---------------------------------------------------------------------------
// Weight transpose (hi only), 4 weights in one launch (blockIdx.z selects):
// W[K,N] fp32 -> Wt hi [N,K] fp16
// ---------------------------------------------------------------------------
struct WPair { const float* W; __half* oh; };

__global__ void wsplit4(WPair w0, WPair w1, WPair w2, WPair w3)
{
    __shared__ float t[32][33];
    const WPair wp = (blockIdx.z == 0) ? w0 : (blockIdx.z == 1) ? w1
                   : (blockIdx.z == 2) ? w2 : w3;
    const int n0 = blockIdx.x * 32, k0 = blockIdx.y * 32;
    const int tx = threadIdx.x, ty = threadIdx.y;
#pragma unroll
    for (int i = 0; i < 32; i += 8)
        t[ty + i][tx] = wp.W[(long)(k0 + ty + i) * EMB + n0 + tx];
    __syncthreads();
#pragma unroll
    for (int i = 0; i < 32; i += 8) {
        const long o = (long)(n0 + ty + i) * EMB + k0 + tx;
        wp.oh[o] = __float2half_rn(t[tx][ty + i]);
    }
}

// ---------------------------------------------------------------------------
// Row softmax over fp16 raw scores, in place, emitting fp16 probs x P_SCALE.
// ---------------------------------------------------------------------------
__global__ void __launch_bounds__(256)
softmax_h(__half* __restrict__ Ph)
{
    __shared__ float sred[8];
    __shared__ float sbc[2];
    const int tid = threadIdx.x;
    const long base = (long)blockIdx.x * SEQ;

    float v[8];
    {
        const uint4 a = *reinterpret_cast<const uint4*>(Ph + base + tid * 8);
        const __half2* h = reinterpret_cast<const __half2*>(&a);
#pragma unroll
        for (int j = 0; j < 4; ++j) {
            float2 f = __half22float2(h[j]);
            v[2 * j]     = f.x;
            v[2 * j + 1] = f.y;
        }
    }

    float m = v[0];
#pragma unroll
    for (int j = 1; j < 8; j++) m = fmaxf(m, v[j]);
#pragma unroll
    for (int o = 16; o > 0; o >>= 1) m = fmaxf(m, __shfl_xor_sync(0xffffffffu, m, o));
    if ((tid & 31) == 0) sred[tid >> 5] = m;
    __syncthreads();
    if (tid == 0) {
        float t = sred[0];
#pragma unroll
        for (int w = 1; w < 8; w++) t = fmaxf(t, sred[w]);
        sbc[0] = t;
    }
    __syncthreads();
    m = sbc[0];

    float s = 0.f;
#pragma unroll
    for (int j = 0; j < 8; j++) { v[j] = __expf(v[j] - m); s += v[j]; }
#pragma unroll
    for (int o = 16; o > 0; o >>= 1) s += __shfl_xor_sync(0xffffffffu, s, o);
    __syncthreads();
    if ((tid & 31) == 0) sred[tid >> 5] = s;
    __syncthreads();
    if (tid == 0) {
        float t = sred[0];
#pragma unroll
        for (int w = 1; w < 8; w++) t += sred[w];
        sbc[1] = t;
    }
    __syncthreads();
    const float inv = P_SCALE / sbc[1];

    uint4 o;
    o.x = pack_h2(__float2half_rn(v[0] * inv), __float2half_rn(v[1] * inv));
    o.y = pack_h2(__float2half_rn(v[2] * inv), __float2half_rn(v[3] * inv));
    o.z = pack_h2(__float2half_rn(v[4] * inv), __float2half_rn(v[5] * inv));
    o.w = pack_h2(__float2half_rn(v[6] * inv), __float2half_rn(v[7] * inv));
    *reinterpret_cast<uint4*>(Ph + base + tid * 8) = o;
}

// ---------------------------------------------------------------------------
// Host side
// ---------------------------------------------------------------------------
extern "C" void kernel_launch(void* const* d_in, const int* in_sizes, int n_in,
                              void* d_out, int out_size)
{
    const float* x  = (const float*)d_in[0];
    const float* Wq = (const float*)d_in[1];
    const float* bq = (const float*)d_in[2];
    const float* Wk = (const float*)d_in[3];
    const float* bk = (const float*)d_in[4];
    const float* Wv = (const float*)d_in[5];
    const float* bv = (const float*)d_in[6];
    const float* Wo = (const float*)d_in[7];
    const float* bo = (const float*)d_in[8];
    float* out = (float*)d_out;

    void *xh, *Wqh, *Wkh, *Wvh, *Woh;
    void *Qh, *Kh, *Vh, *Ph, *Ch;
    cudaGetSymbolAddress(&xh, g_xh);
    cudaGetSymbolAddress(&Wqh, g_Wqh);
    cudaGetSymbolAddress(&Wkh, g_Wkh);
    cudaGetSymbolAddress(&Wvh, g_Wvh);
    cudaGetSymbolAddress(&Woh, g_Woh);
    cudaGetSymbolAddress(&Qh, g_Qh);
    cudaGetSymbolAddress(&Kh, g_Kh);
    cudaGetSymbolAddress(&Vh, g_Vh);
    cudaGetSymbolAddress(&Ph, g_Ph);
    cudaGetSymbolAddress(&Ch, g_Ch);

    const int SM2 = NSTAGE * STAGEB;     // 110592 (gemm_mma: 3 stages x 2 tiles)
    const int SMP = PV_NST * PV_STAGE;   // 104448 (PV: 3 stages)
    cudaFuncSetAttribute(gemm_mma<0>, cudaFuncAttributeMaxDynamicSharedMemorySize, SM2);
    cudaFuncSetAttribute(gemm_mma<1>, cudaFuncAttributeMaxDynamicSharedMemorySize, SM2);
    cudaFuncSetAttribute(gemm_pv,     cudaFuncAttributeMaxDynamicSharedMemorySize, SMP);

    const float scl = 1.0f / sqrtf((float)EMB);
    const dim3 blk(256);
    const BSeg nil = {nullptr, nullptr, nullptr, 1.0f};

    // 1) convert inputs to fp16 hi (x + all 4 weights, 2 launches)
    {
        const int n8 = MROWS * EMB / 8;
        cvt_h<<<(n8 + 255) / 256, 256>>>((const float4*)x, (__half*)xh, n8);
        WPair w0 = {Wq, (__half*)Wqh};
        WPair w1 = {Wk, (__half*)Wkh};
        WPair w2 = {Wv, (__half*)Wvh};
        WPair w3 = {Wo, (__half*)Woh};
        wsplit4<<<dim3(24, 24, 4), dim3(32, 8)>>>(w0, w1, w2, w3);
    }

    // 2) merged QKV projections: one launch, segmented B/out, hi out
    {
        BSeg sq = {(const __half*)Wqh, bq, (__half*)Qh, scl};
        BSeg sk = {(const __half*)Wkh, bk, (__half*)Kh, 1.0f};
        BSeg sv = {(const __half*)Wvh, bv, (__half*)Vh, 1.0f};
        gemm_mma<1><<<dim3(18, 128, 1), blk, SM2>>>(
            (const __half*)xh,
            EMB, EMB, EMB, 0, 0,
            nullptr, EMB, 0, sq, sk, sv, 6);
    }

    // 3) scores = Q' @ K^T (scale folded into Q), fp16 raw scores out
    {
        BSeg sc = {(const __half*)Kh, nullptr, (__half*)Ph, 1.0f};
        gemm_mma<1><<<dim3(16, 16, 8), blk, SM2>>>(
            (const __half*)Qh,
            EMB, EMB, EMB, (long)SEQ * EMB, (long)SEQ * EMB,
            nullptr, SEQ, (long)SEQ * SEQ, sc, nil, nil, 0);
    }

    // 4) softmax in place: fp16 scores -> fp16 probs (x P_SCALE)
    softmax_h<<<MROWS, 256>>>((__half*)Ph);

    // 5) ctx = P @ V, B = V row-major via trans-ldmatrix, K=2048
    gemm_pv<<<dim3(6, 16, 8), blk, SMP>>>(
        (const __half*)Ph, (const __half*)Vh,
        SEQ, SEQ, EMB, (long)SEQ * SEQ, (long)SEQ * EMB,
        (__half*)Ch, 1.0f / P_SCALE, EMB, (long)SEQ * EMB);

    // 6) out = C @ Wo^T + bo, fp32
    {
        BSeg so = {(const __half*)Woh, bo, nullptr, 1.0f};
        gemm_mma<0><<<dim3(6, 128, 1), blk, SM2>>>(
            (const __half*)Ch,
            EMB, EMB, EMB, 0, 0,
            out, EMB, 0, so, nil, nil, 0);
    }
}

// round 17
// speedup vs baseline: 1.1697x; 1.1002x over previous
#include <cuda_runtime.h>
#include <cuda_fp16.h>
#include <math.h>
#include <stdint.h>

#define BSZ 8
#define SEQ 2048
#define EMB 768
#define MROWS (BSZ*SEQ)
#define P_SCALE 1024.0f

// ---------------------------------------------------------------------------
// Scratch (device globals; allocation forbidden in kernel_launch)
// ---------------------------------------------------------------------------
__device__ __align__(256) __half g_xh[MROWS*EMB];
__device__ __align__(256) __half g_Wqh[EMB*EMB];
__device__ __align__(256) __half g_Wkh[EMB*EMB];
__device__ __align__(256) __half g_Wvh[EMB*EMB];
__device__ __align__(256) __half g_Woh[EMB*EMB];
__device__ __align__(256) __half g_Qh[MROWS*EMB];
__device__ __align__(256) __half g_Kh[MROWS*EMB];
__device__ __align__(256) __half g_Vh[MROWS*EMB];                  // V hi, row-major [b,s,e]
__device__ __align__(256) __half g_Ph[(size_t)BSZ*SEQ*SEQ];        // fp16 scores -> probs (in place)
__device__ __align__(256) __half g_Ch[MROWS*EMB];

// ---------------------------------------------------------------------------
// helpers
// ---------------------------------------------------------------------------
__device__ __forceinline__ uint32_t smem_u32(const void* p) {
    uint32_t a;
    asm("{ .reg .u64 t; cvta.to.shared.u64 t, %1; cvt.u32.u64 %0, t; }" : "=r"(a) : "l"(p));
    return a;
}
__device__ __forceinline__ void cpasync16(uint32_t s, const void* g) {
    asm volatile("cp.async.cg.shared.global [%0], [%1], 16;" :: "r"(s), "l"(g));
}
__device__ __forceinline__ void cp_commit() { asm volatile("cp.async.commit_group;"); }

__device__ __forceinline__ void ldm_x4(uint32_t (&r)[4], uint32_t a) {
    asm volatile("ldmatrix.sync.aligned.m8n8.x4.shared.b16 {%0,%1,%2,%3}, [%4];"
        : "=r"(r[0]), "=r"(r[1]), "=r"(r[2]), "=r"(r[3]) : "r"(a));
}
__device__ __forceinline__ void ldm_x4_t(uint32_t (&r)[4], uint32_t a) {
    asm volatile("ldmatrix.sync.aligned.m8n8.x4.trans.shared.b16 {%0,%1,%2,%3}, [%4];"
        : "=r"(r[0]), "=r"(r[1]), "=r"(r[2]), "=r"(r[3]) : "r"(a));
}
__device__ __forceinline__ void mma16816(float (&d)[4], const uint32_t (&a)[4],
                                         uint32_t b0, uint32_t b1) {
    asm volatile("mma.sync.aligned.m16n8k16.row.col.f32.f16.f16.f32 "
        "{%0,%1,%2,%3}, {%4,%5,%6,%7}, {%8,%9}, {%0,%1,%2,%3};"
        : "+f"(d[0]), "+f"(d[1]), "+f"(d[2]), "+f"(d[3])
        : "r"(a[0]), "r"(a[1]), "r"(a[2]), "r"(a[3]), "r"(b0), "r"(b1));
}
__device__ __forceinline__ uint32_t pack_h2(__half a, __half b) {
    __half2 t(a, b);
    return *reinterpret_cast<uint32_t*>(&t);
}

// K-chunk = 64 halfs: row = 128B data + 16B pad (conflict-free ldmatrix)
#define ROWB   144
#define TILEB  (128*ROWB)               // 18432 B

// Per-segment output descriptor (passed by value; selected per CTA by blockIdx.x)
struct BSeg {
    const __half* Bh;
    const float*  bias;
    __half*       outHi;
    float         scale;
};

// ---------------------------------------------------------------------------
// fp16 warp-MMA GEMM: D[m,n] = sum_k A[m,k]*B[n,k] (both K-major), fp32 accum.
// CTA 128x128, Kc=64, 8 warps (32x64), single-sync 3-stage cp.async, 2 CTA/SM.
// Global loads for chunk kc+2 are interleaved across the 4 ks compute steps
// (2 cp.async per step) to smooth post-barrier LSU/L1 bursts.
// OUTMODE 0: fp32 out (+bias). OUTMODE 1: fp16 hi out ((acc+bias)*scale).
// Segmented B: CTAs pick {s0,s1,s2} by blockIdx.x / segW (merged QKV launch).
// ---------------------------------------------------------------------------
#define NSTAGE 3
#define STAGEB (2*TILEB)                // 36864

template <int OUTMODE>
__global__ void __launch_bounds__(256, 2)
gemm_mma(const __half* __restrict__ Ah,
         int K, long ldA, long ldB, long sAb, long sBb,
         float* __restrict__ outF, long ldOut, long obs,
         BSeg s0, BSeg s1, BSeg s2, int segW)
{
    extern __shared__ char smem[];
    const uint32_t sb = smem_u32(smem);

    const int tid    = threadIdx.x;
    const int lane   = tid & 31;
    const int wid    = tid >> 5;
    const int warp_m = wid & 3;
    const int warp_n = wid >> 2;

    int bxi = blockIdx.x;
    BSeg seg = s0;
    if (segW > 0) {
        if (bxi >= 2 * segW)      { seg = s2; bxi -= 2 * segW; }
        else if (bxi >= segW)     { seg = s1; bxi -= segW; }
    }
    const int by = blockIdx.y * 128;
    const int bx = bxi * 128;
    const int bz = blockIdx.z;

    Ah += (long)bz * sAb;
    const __half* Bh = seg.Bh + (long)bz * sBb;

    // full-chunk loader (prologue only): 1024 16B-chunks/tile, 4/thread/tile
    auto load_chunk = [&](int kc, int stage) {
        const long kk = (long)kc * 64;
        const uint32_t s0a = sb + stage * STAGEB;
#pragma unroll
        for (int i = 0; i < 4; ++i) {
            const int c   = tid + i * 256;
            const int row = c >> 3;
            const int g   = c & 7;
            cpasync16(s0a + row * ROWB + g * 16,
                      Ah + (long)(by + row) * ldA + kk + g * 8);
            cpasync16(s0a + TILEB + row * ROWB + g * 16,
                      Bh + (long)(bx + row) * ldB + kk + g * 8);
        }
    };

    float acc[2][8][4];
#pragma unroll
    for (int i = 0; i < 2; ++i)
#pragma unroll
        for (int j = 0; j < 8; ++j)
#pragma unroll
            for (int e = 0; e < 4; ++e) acc[i][j][e] = 0.f;

    const int nChunks = K >> 6;

#pragma unroll
    for (int i = 0; i < NSTAGE - 1; ++i) {
        load_chunk(i, i);
        cp_commit();
    }

    const int rl = lane & 7;
    const int gq = lane >> 3;
    const uint32_t aoff = (uint32_t)((warp_m * 32 + (gq & 1) * 8 + rl) * ROWB + (gq >> 1) * 16);
    const uint32_t boff = (uint32_t)((warp_n * 64 + (gq >> 1) * 8 + rl) * ROWB + (gq & 1) * 16);

    // single-sync loop: wait(kc ready) -> sync -> [per-ks: issue 2 loads of
    // chunk kc+2 into slot (kc-1)%NSTAGE, then compute ks] -> commit group
    for (int kc = 0; kc < nChunks; ++kc) {
        asm volatile("cp.async.wait_group %0;" :: "n"(NSTAGE - 2));
        __syncthreads();
        const int  pf     = kc + NSTAGE - 1;
        const bool doLoad = (pf < nChunks);
        const long kkp    = (long)pf * 64;
        const uint32_t sp = sb + (pf % NSTAGE) * STAGEB;
        const uint32_t st = sb + (kc % NSTAGE) * STAGEB;

#pragma unroll
        for (int ks = 0; ks < 4; ++ks) {
            if (doLoad) {
                const int c   = tid + ks * 256;
                const int row = c >> 3;
                const int g   = c & 7;
                cpasync16(sp + row * ROWB + g * 16,
                          Ah + (long)(by + row) * ldA + kkp + g * 8);
                cpasync16(sp + TILEB + row * ROWB + g * 16,
                          Bh + (long)(bx + row) * ldB + kkp + g * 8);
            }
            const uint32_t kb = ks * 32;
            uint32_t ah[2][4];
#pragma unroll
            for (int i = 0; i < 2; ++i)
                ldm_x4(ah[i], st + aoff + i * (16 * ROWB) + kb);
            uint32_t bh[4][4];
#pragma unroll
            for (int g = 0; g < 4; ++g)
                ldm_x4(bh[g], st + TILEB + boff + g * (16 * ROWB) + kb);
#pragma unroll
            for (int i = 0; i < 2; ++i)
#pragma unroll
                for (int j = 0; j < 8; ++j) {
                    const int g = j >> 1, o = (j & 1) * 2;
                    mma16816(acc[i][j], ah[i], bh[g][o], bh[g][o + 1]);
                }
        }
        cp_commit();
    }

    // ---------------- epilogue ----------------
    const int r_in = lane >> 2;
    const int c_in = (lane & 3) * 2;

#pragma unroll
    for (int i = 0; i < 2; ++i) {
#pragma unroll
        for (int j = 0; j < 8; ++j) {
            const int row0 = by + warp_m * 32 + i * 16 + r_in;
            const int row1 = row0 + 8;
            const int col  = bx + warp_n * 64 + j * 8 + c_in;
            const float b0 = seg.bias ? seg.bias[col]     : 0.f;
            const float b1 = seg.bias ? seg.bias[col + 1] : 0.f;

            if (OUTMODE == 0) {
                float2 v0 = make_float2(acc[i][j][0] + b0, acc[i][j][1] + b1);
                float2 v1 = make_float2(acc[i][j][2] + b0, acc[i][j][3] + b1);
                *reinterpret_cast<float2*>(outF + (long)bz * obs + (long)row0 * ldOut + col) = v0;
                *reinterpret_cast<float2*>(outF + (long)bz * obs + (long)row1 * ldOut + col) = v1;
            } else {
                float v00 = (acc[i][j][0] + b0) * seg.scale, v01 = (acc[i][j][1] + b1) * seg.scale;
                float v10 = (acc[i][j][2] + b0) * seg.scale, v11 = (acc[i][j][3] + b1) * seg.scale;
                const long o0 = (long)bz * obs + (long)row0 * ldOut + col;
                const long o1 = (long)bz * obs + (long)row1 * ldOut + col;
                *reinterpret_cast<uint32_t*>(seg.outHi + o0) =
                    pack_h2(__float2half_rn(v00), __float2half_rn(v01));
                *reinterpret_cast<uint32_t*>(seg.outHi + o1) =
                    pack_h2(__float2half_rn(v10), __float2half_rn(v11));
            }
        }
    }
}

// ---------------------------------------------------------------------------
// PV GEMM: C[m,e] = sum_s P[m,s] * V[s,e]. A = Ph K-major; B = V row-major
// [s,e] loaded via trans-ldmatrix from swizzled [k=64 x 256B] smem tiles.
// Single-sync 3-stage pipeline, Kc=64, 2 CTA/SM, interleaved loads.
// ---------------------------------------------------------------------------
#define PV_BTILE 16384                       // 64 rows x 256B, swizzled
#define PV_STAGE (TILEB + PV_BTILE)          // 34816
#define PV_NST   3

__global__ void __launch_bounds__(256, 2)
gemm_pv(const __half* __restrict__ Ah, const __half* __restrict__ Bv,
        int K, long ldA, long ldB, long sAb, long sBb,
        __half* __restrict__ outHi, float scale, long ldOut, long obs)
{
    extern __shared__ char smem[];
    const uint32_t sb = smem_u32(smem);

    const int tid    = threadIdx.x;
    const int lane   = tid & 31;
    const int wid    = tid >> 5;
    const int warp_m = wid & 3;
    const int warp_n = wid >> 2;
    const int by     = blockIdx.y * 128;
    const int bx     = blockIdx.x * 128;
    const int bz     = blockIdx.z;

    Ah += (long)bz * sAb;
    Bv += (long)bz * sBb;

    auto load_chunk = [&](int kc, int stage) {
        const long kk = (long)kc * 64;
        const uint32_t s0 = sb + stage * PV_STAGE;
#pragma unroll
        for (int i = 0; i < 4; ++i) {
            const int c   = tid + i * 256;
            const int row = c >> 3;
            const int g   = c & 7;
            cpasync16(s0 + row * ROWB + g * 16,
                      Ah + (long)(by + row) * ldA + kk + g * 8);
        }
        const uint32_t b0 = s0 + TILEB;
#pragma unroll
        for (int i = 0; i < 4; ++i) {
            const int c  = tid + i * 256;
            const int bk = c >> 4;
            const int bg = c & 15;
            cpasync16(b0 + bk * 256 + ((bg ^ (bk & 7)) * 16),
                      Bv + (long)(kk + bk) * ldB + bx + bg * 8);
        }
    };

    float acc[2][8][4];
#pragma unroll
    for (int i = 0; i < 2; ++i)
#pragma unroll
        for (int j = 0; j < 8; ++j)
#pragma unroll
            for (int e = 0; e < 4; ++e) acc[i][j][e] = 0.f;

    const int nChunks = K >> 6;

#pragma unroll
    for (int i = 0; i < PV_NST - 1; ++i) {
        load_chunk(i, i);
        cp_commit();
    }

    const int rl = lane & 7;
    const int gq = lane >> 3;
    const uint32_t aoff = (uint32_t)((warp_m * 32 + (gq & 1) * 8 + rl) * ROWB + (gq >> 1) * 16);
    const int brow_in = (gq & 1) * 8 + rl;            // k within 16-block
    const int bcol16  = warp_n * 8 + (gq >> 1);       // + g*2 at use site

    for (int kc = 0; kc < nChunks; ++kc) {
        asm volatile("cp.async.wait_group %0;" :: "n"(PV_NST - 2));
        __syncthreads();
        const int  pf     = kc + PV_NST - 1;
        const bool doLoad = (pf < nChunks);
        const long kkp    = (long)pf * 64;
        const uint32_t sp = sb + (pf % PV_NST) * PV_STAGE;
        const uint32_t st = sb + (kc % PV_NST) * PV_STAGE;
        const uint32_t bt0 = st + TILEB;

#pragma unroll
        for (int ks = 0; ks < 4; ++ks) {
            if (doLoad) {
                const int c   = tid + ks * 256;
                const int row = c >> 3;
                const int g   = c & 7;
                cpasync16(sp + row * ROWB + g * 16,
                          Ah + (long)(by + row) * ldA + kkp + g * 8);
                const int bk = c >> 4;
                const int bg = c & 15;
                cpasync16(sp + TILEB + bk * 256 + ((bg ^ (bk & 7)) * 16),
                          Bv + (long)(kkp + bk) * ldB + bx + bg * 8);
            }
            uint32_t ah[2][4];
#pragma unroll
            for (int i = 0; i < 2; ++i)
                ldm_x4(ah[i], st + aoff + i * (16 * ROWB) + ks * 32);
            uint32_t bt[4][4];
            const int row = ks * 16 + brow_in;
#pragma unroll
            for (int g = 0; g < 4; ++g) {
                const int c = (bcol16 + g * 2) ^ (row & 7);
                ldm_x4_t(bt[g], bt0 + row * 256 + c * 16);
            }
#pragma unroll
            for (int i = 0; i < 2; ++i)
#pragma unroll
                for (int j = 0; j < 8; ++j) {
                    const int g = j >> 1, o = (j & 1) * 2;
                    mma16816(acc[i][j], ah[i], bt[g][o], bt[g][o + 1]);
                }
        }
        cp_commit();
    }

    // epilogue: hi only, *scale
    const int r_in = lane >> 2;
    const int c_in = (lane & 3) * 2;
#pragma unroll
    for (int i = 0; i < 2; ++i) {
#pragma unroll
        for (int j = 0; j < 8; ++j) {
            const int row0 = by + warp_m * 32 + i * 16 + r_in;
            const int row1 = row0 + 8;
            const int col  = bx + warp_n * 64 + j * 8 + c_in;
            float v00 = acc[i][j][0] * scale, v01 = acc[i][j][1] * scale;
            float v10 = acc[i][j][2] * scale, v11 = acc[i][j][3] * scale;
            const long o0 = (long)bz * obs + (long)row0 * ldOut + col;
            const long o1 = (long)bz * obs + (long)row1 * ldOut + col;
            *reinterpret_cast<uint32_t*>(outHi + o0) =
                pack_h2(__float2half_rn(v00), __float2half_rn(v01));
            *reinterpret_cast<uint32_t*>(outHi + o1) =
                pack_h2(__float2half_rn(v10), __float2half_rn(v11));
        }
    }
}

// ---------------------------------------------------------------------------
// Elementwise convert: fp32 -> fp16 (hi only), 8 elems/thread
// ---------------------------------------------------------------------------
__global__ void cvt_h(const float4* __restrict__ in, __half* __restrict__ oh, int n8)
{
    const int i = blockIdx.x * blockDim.x + threadIdx.x;
    if (i >= n8) return;
    const float4 a = in[2 * i];
    const float4 b = in[2 * i + 1];
    uint4 o;
    o.x = pack_h2(__float2half_rn(a.x), __float2half_rn(a.y));
    o.y = pack_h2(__float2half_rn(a.z), __float2half_rn(a.w));
    o.z = pack_h2(__float2half_rn(b.x), __float2half_rn(b.y));
    o.w = pack_h2(__float2half_rn(b.z), __float2half_rn(b.w));
    *reinterpret_cast<uint4*>(oh + 8 * (long)i) = o;
}

// ---------------------------------------------------------------------------
// Weight transpose (hi only), 4 weights in one launch (blockIdx.z selects):
// W[K,N] fp32 -> Wt hi [N,K] fp16
// ---------------------------------------------------------------------------
struct WPair { const float* W; __half* oh; };

__global__ void wsplit4(WPair w0, WPair w1, WPair w2, WPair w3)
{
    __shared__ float t[32][33];
    const WPair wp = (blockIdx.z == 0) ? w0 : (blockIdx.z == 1) ? w1
                   : (blockIdx.z == 2) ? w2 : w3;
    const int n0 = blockIdx.x * 32, k0 = blockIdx.y * 32;
    const int tx = threadIdx.x, ty = threadIdx.y;
#pragma unroll
    for (int i = 0; i < 32; i += 8)
        t[ty + i][tx] = wp.W[(long)(k0 + ty + i) * EMB + n0 + tx];
    __syncthreads();
#pragma unroll
    for (int i = 0; i < 32; i += 8) {
        const long o = (long)(n0 + ty + i) * EMB + k0 + tx;
        wp.oh[o] = __float2half_rn(t[tx][ty + i]);
    }
}

// ---------------------------------------------------------------------------
// Row softmax over fp16 raw scores, in place, emitting fp16 probs x P_SCALE.
// ---------------------------------------------------------------------------
__global__ void __launch_bounds__(256)
softmax_h(__half* __restrict__ Ph)
{
    __shared__ float sred[8];
    __shared__ float sbc[2];
    const int tid = threadIdx.x;
    const long base = (long)blockIdx.x * SEQ;

    float v[8];
    {
        const uint4 a = *reinterpret_cast<const uint4*>(Ph + base + tid * 8);
        const __half2* h = reinterpret_cast<const __half2*>(&a);
#pragma unroll
        for (int j = 0; j < 4; ++j) {
            float2 f = __half22float2(h[j]);
            v[2 * j]     = f.x;
            v[2 * j + 1] = f.y;
        }
    }

    float m = v[0];
#pragma unroll
    for (int j = 1; j < 8; j++) m = fmaxf(m, v[j]);
#pragma unroll
    for (int o = 16; o > 0; o >>= 1) m = fmaxf(m, __shfl_xor_sync(0xffffffffu, m, o));
    if ((tid & 31) == 0) sred[tid >> 5] = m;
    __syncthreads();
    if (tid == 0) {
        float t = sred[0];
#pragma unroll
        for (int w = 1; w < 8; w++) t = fmaxf(t, sred[w]);
        sbc[0] = t;
    }
    __syncthreads();
    m = sbc[0];

    float s = 0.f;
#pragma unroll
    for (int j = 0; j < 8; j++) { v[j] = __expf(v[j] - m); s += v[j]; }
#pragma unroll
    for (int o = 16; o > 0; o >>= 1) s += __shfl_xor_sync(0xffffffffu, s, o);
    __syncthreads();
    if ((tid & 31) == 0) sred[tid >> 5] = s;
    __syncthreads();
    if (tid == 0) {
        float t = sred[0];
#pragma unroll
        for (int w = 1; w < 8; w++) t += sred[w];
        sbc[1] = t;
    }
    __syncthreads();
    const float inv = P_SCALE / sbc[1];

    uint4 o;
    o.x = pack_h2(__float2half_rn(v[0] * inv), __float2half_rn(v[1] * inv));
    o.y = pack_h2(__float2half_rn(v[2] * inv), __float2half_rn(v[3] * inv));
    o.z = pack_h2(__float2half_rn(v[4] * inv), __float2half_rn(v[5] * inv));
    o.w = pack_h2(__float2half_rn(v[6] * inv), __float2half_rn(v[7] * inv));
    *reinterpret_cast<uint4*>(Ph + base + tid * 8) = o;
}

// ---------------------------------------------------------------------------
// Host side
// ---------------------------------------------------------------------------
extern "C" void kernel_launch(void* const* d_in, const int* in_sizes, int n_in,
                              void* d_out, int out_size)
{
    const float* x  = (const float*)d_in[0];
    const float* Wq = (const float*)d_in[1];
    const float* bq = (const float*)d_in[2];
    const float* Wk = (const float*)d_in[3];
    const float* bk = (const float*)d_in[4];
    const float* Wv = (const float*)d_in[5];
    const float* bv = (const float*)d_in[6];
    const float* Wo = (const float*)d_in[7];
    const float* bo = (const float*)d_in[8];
    float* out = (float*)d_out;

    void *xh, *Wqh, *Wkh, *Wvh, *Woh;
    void *Qh, *Kh, *Vh, *Ph, *Ch;
    cudaGetSymbolAddress(&xh, g_xh);
    cudaGetSymbolAddress(&Wqh, g_Wqh);
    cudaGetSymbolAddress(&Wkh, g_Wkh);
    cudaGetSymbolAddress(&Wvh, g_Wvh);
    cudaGetSymbolAddress(&Woh, g_Woh);
    cudaGetSymbolAddress(&Qh, g_Qh);
    cudaGetSymbolAddress(&Kh, g_Kh);
    cudaGetSymbolAddress(&Vh, g_Vh);
    cudaGetSymbolAddress(&Ph, g_Ph);
    cudaGetSymbolAddress(&Ch, g_Ch);

    const int SM2 = NSTAGE * STAGEB;     // 110592 (gemm_mma: 3 stages x 2 tiles)
    const int SMP = PV_NST * PV_STAGE;   // 104448 (PV: 3 stages)
    cudaFuncSetAttribute(gemm_mma<0>, cudaFuncAttributeMaxDynamicSharedMemorySize, SM2);
    cudaFuncSetAttribute(gemm_mma<1>, cudaFuncAttributeMaxDynamicSharedMemorySize, SM2);
    cudaFuncSetAttribute(gemm_pv,     cudaFuncAttributeMaxDynamicSharedMemorySize, SMP);

    const float scl = 1.0f / sqrtf((float)EMB);
    const dim3 blk(256);
    const BSeg nil = {nullptr, nullptr, nullptr, 1.0f};

    // 1) convert inputs to fp16 hi (x + all 4 weights, 2 launches)
    {
        const int n8 = MROWS * EMB / 8;
        cvt_h<<<(n8 + 255) / 256, 256>>>((const float4*)x, (__half*)xh, n8);
        WPair w0 = {Wq, (__half*)Wqh};
        WPair w1 = {Wk, (__half*)Wkh};
        WPair w2 = {Wv, (__half*)Wvh};
        WPair w3 = {Wo, (__half*)Woh};
        wsplit4<<<dim3(24, 24, 4), dim3(32, 8)>>>(w0, w1, w2, w3);
    }

    // 2) merged QKV projections: one launch, segmented B/out, hi out
    {
        BSeg sq = {(const __half*)Wqh, bq, (__half*)Qh, scl};
        BSeg sk = {(const __half*)Wkh, bk, (__half*)Kh, 1.0f};
        BSeg sv = {(const __half*)Wvh, bv, (__half*)Vh, 1.0f};
        gemm_mma<1><<<dim3(18, 128, 1), blk, SM2>>>(
            (const __half*)xh,
            EMB, EMB, EMB, 0, 0,
            nullptr, EMB, 0, sq, sk, sv, 6);
    }

    // 3) scores = Q' @ K^T (scale folded into Q), fp16 raw scores out
    {
        BSeg sc = {(const __half*)Kh, nullptr, (__half*)Ph, 1.0f};
        gemm_mma<1><<<dim3(16, 16, 8), blk, SM2>>>(
            (const __half*)Qh,
            EMB, EMB, EMB, (long)SEQ * EMB, (long)SEQ * EMB,
            nullptr, SEQ, (long)SEQ * SEQ, sc, nil, nil, 0);
    }

    // 4) softmax in place: fp16 scores -> fp16 probs (x P_SCALE)
    softmax_h<<<MROWS, 256>>>((__half*)Ph);

    // 5) ctx = P @ V, B = V row-major via trans-ldmatrix, K=2048
    gemm_pv<<<dim3(6, 16, 8), blk, SMP>>>(
        (const __half*)Ph, (const __half*)Vh,
        SEQ, SEQ, EMB, (long)SEQ * SEQ, (long)SEQ * EMB,
        (__half*)Ch, 1.0f / P_SCALE, EMB, (long)SEQ * EMB);

    // 6) out = C @ Wo^T + bo, fp32
    {
        BSeg so = {(const __half*)Woh, bo, nullptr, 1.0f};
        gemm_mma<0><<<dim3(6, 128, 1), blk, SM2>>>(
            (const __half*)Ch,
            EMB, EMB, EMB, 0, 0,
            out, EMB, 0, so, nil, nil, 0);
    }
}